// round 8
// baseline (speedup 1.0000x reference)
#include <cuda_runtime.h>
#include <cuda_fp16.h>
#include <cstdint>

// ---------------------------------------------------------------------------
// LocalizedFiltering via shifted-pair GEMMs on mma.sync fp16 tensor cores.
//   O1[t] = W1_0 @ xprev(t) + W1_1 @ x[t] + b1
//   pre[t]= W2_0 @ o1prev(t)+ W2_1 @ O1[t]+ b2 + x[t]
//   out[t]= RMSNorm(pre[t]) * gamma
// Precision: single fp16 A and W, fp32 accumulate (2 products per output).
// Pipeline: BK=64, 2-stage cp.async ring (wait_group 1), BM=128 BN=256,
// 256 threads / 8 warps with 64x64 warp tiles. 256 mma/warp between syncs.
// Output: [lf_output total*E][lf1 B*E][lf2 B*H]
// ---------------------------------------------------------------------------

#define MAX_TOTAL 24576
#define MAX_E     2048
#define MAX_H     1024
#define MAX_B     64

#define A_TILE   16384         // 128 rows * 128B (per variant)
#define B_OFF    32768         // 2 A tiles
#define B_TILE   32768         // 256 rows * 128B (per variant)
#define STAGE    98304
#define NSTAGE   2
#define DYN_SMEM (STAGE * NSTAGE)

// scratch (static __device__; no cudaMalloc allowed)
__device__ __half g_Xh [(size_t)MAX_TOTAL * MAX_E];
__device__ __half g_O1h[(size_t)MAX_TOTAL * MAX_H];
__device__ __half g_W1f[(size_t)2 * MAX_H * MAX_E]; // [var][n*E+k]
__device__ __half g_W2f[(size_t)2 * MAX_E * MAX_H]; // [var][n*H+k]
__device__ float  g_pre[(size_t)MAX_TOTAL * MAX_E];
__device__ __half g_bndXh[MAX_B * MAX_E];
__device__ __half g_bndOh[MAX_B * MAX_H];
__device__ int    g_tokseq[MAX_TOTAL];

// ---------------------------------------------------------------------------
// helpers
// ---------------------------------------------------------------------------
__device__ __forceinline__ uint32_t smem_u32(const void* p) {
    return (uint32_t)__cvta_generic_to_shared(p);
}
__device__ __forceinline__ void cp16(uint32_t dst, const void* src) {
    asm volatile("cp.async.cg.shared.global [%0], [%1], 16;" :: "r"(dst), "l"(src) : "memory");
}
__device__ __forceinline__ void cp_commit() {
    asm volatile("cp.async.commit_group;" ::: "memory");
}
__device__ __forceinline__ void cp_wait1() {
    asm volatile("cp.async.wait_group 1;" ::: "memory");
}
__device__ __forceinline__ void ldsm_x4(uint32_t* r, uint32_t a) {
    asm volatile("ldmatrix.sync.aligned.m8n8.x4.shared.b16 {%0,%1,%2,%3}, [%4];"
                 : "=r"(r[0]), "=r"(r[1]), "=r"(r[2]), "=r"(r[3]) : "r"(a));
}
__device__ __forceinline__ void mma_fp16(float* c, const uint32_t* a, const uint32_t* b) {
    asm volatile("mma.sync.aligned.m16n8k16.row.col.f32.f16.f16.f32 "
                 "{%0,%1,%2,%3}, {%4,%5,%6,%7}, {%8,%9}, {%0,%1,%2,%3};"
                 : "+f"(c[0]), "+f"(c[1]), "+f"(c[2]), "+f"(c[3])
                 : "r"(a[0]), "r"(a[1]), "r"(a[2]), "r"(a[3]), "r"(b[0]), "r"(b[1]));
}
// 128B-row tile: byte offset for (row, chunk[0..7]) — SW128, conflict-free ldsm
__device__ __forceinline__ uint32_t swz128(int row, int chunk) {
    return (uint32_t)(row * 128 + ((chunk ^ (row & 7)) << 4));
}

// ---------------------------------------------------------------------------
// prep kernels
// ---------------------------------------------------------------------------
__global__ void split_x_kernel(const float* __restrict__ x, size_t n)
{
    size_t i = ((size_t)blockIdx.x * blockDim.x + threadIdx.x) * 4;
    size_t stride = (size_t)gridDim.x * blockDim.x * 4;
    for (; i < n; i += stride) {
        float4 v = *(const float4*)(x + i);
        *(__half2*)(g_Xh + i)     = __floats2half2_rn(v.x, v.y);
        *(__half2*)(g_Xh + i + 2) = __floats2half2_rn(v.z, v.w);
    }
}

__global__ void pack_w_kernel(const float* __restrict__ w1,
                              const float* __restrict__ w2, int E, int H)
{
    size_t stride = (size_t)gridDim.x * blockDim.x;
    size_t i0 = (size_t)blockIdx.x * blockDim.x + threadIdx.x;
    size_t n1 = (size_t)H * E;
    for (size_t i = i0; i < n1; i += stride) {
        g_W1f[i]      = __float2half_rn(w1[i * 2]);
        g_W1f[n1 + i] = __float2half_rn(w1[i * 2 + 1]);
    }
    size_t n2 = (size_t)E * H;
    for (size_t i = i0; i < n2; i += stride) {
        g_W2f[i]      = __float2half_rn(w2[i * 2]);
        g_W2f[n2 + i] = __float2half_rn(w2[i * 2 + 1]);
    }
}

__global__ void prep_tok_kernel(const int* __restrict__ start, int B, int total)
{
    int t = blockIdx.x * blockDim.x + threadIdx.x;
    if (t >= total) return;
    int lo = 0, hi = B - 1;
    while (lo < hi) {
        int mid = (lo + hi + 1) >> 1;
        if (start[mid] <= t) lo = mid; else hi = mid - 1;
    }
    g_tokseq[t] = lo;
}

__global__ void prep_bnd_kernel(const float* __restrict__ lf1,
                                const float* __restrict__ lf2,
                                const float* __restrict__ w1,
                                const float* __restrict__ b1,
                                const int*   __restrict__ lens,
                                const int*   __restrict__ maxlen_ptr,
                                int E, int H)
{
    int b = blockIdx.x;
    int L = lens[b];
    int ml = maxlen_ptr ? maxlen_ptr[0] : 4096;
    bool full = (L == ml);
    for (int i = threadIdx.x; i < E; i += blockDim.x) {
        float v = full ? lf1[(size_t)b * E + i] : 0.f;
        g_bndXh[(size_t)b * E + i] = __float2half_rn(v);
    }
    int s0 = ml - L;
    for (int n = threadIdx.x; n < H; n += blockDim.x) {
        float v;
        if (full) {
            v = lf2[(size_t)b * H + n];
        } else {
            v = b1[n];
            if (s0 == 1) {
                const float* wr = w1 + (size_t)n * E * 2;
                float acc = 0.f;
                for (int k = 0; k < E; k++) acc += wr[(size_t)k * 2] * lf1[(size_t)b * E + k];
                v += acc;
            }
        }
        g_bndOh[(size_t)b * H + n] = __float2half_rn(v);
    }
}

// ---------------------------------------------------------------------------
// Shifted-pair fp16 GEMM. BM=128 BN=256 BK=64, 256 threads (8 warps, 64x64).
// A variants in smem: 0=prev 1=cur; B variants: 0=W0 1=W1.
// ---------------------------------------------------------------------------
template<bool STAGE2>
__global__ __launch_bounds__(256, 1)
void conv_tc(const __half* __restrict__ srcH,
             const __half* __restrict__ bndH,
             const __half* __restrict__ Wf, size_t wvar,
             const float* __restrict__ bias,
             const float* __restrict__ resid,
             const int* __restrict__ start,
             int M, int Nfull, int K,
             float* __restrict__ outF,
             __half* __restrict__ outH)
{
    extern __shared__ char sm[];
    const uint32_t sbase = smem_u32(sm);
    const int tid = threadIdx.x;
    const int lane = tid & 31;
    const int wid = tid >> 5;
    const int m0 = blockIdx.y * 128;
    const int n0 = blockIdx.x * 256;

    // ---- cp.async assignment: one full 128B row per thread per tile --------
    // A: 2 variants x 128 rows = 256 rows -> 1 per thread (8 cp16)
    const __half* aptr; uint32_t adstb; int arow7;
    {
        int var = tid >> 7;          // 0=prev 1=cur
        int row = tid & 127;
        int t = m0 + row; if (t >= M) t = M - 1;
        if (var == 0) {
            int b = g_tokseq[t];
            aptr = (t == start[b]) ? (bndH + (size_t)b * K)
                                   : (srcH + (size_t)(t - 1) * K);
        } else {
            aptr = srcH + (size_t)t * K;
        }
        adstb = (uint32_t)(var * A_TILE + row * 128);
        arow7 = row & 7;
    }
    // B: 2 variants x 256 rows = 512 rows -> 2 per thread (8 cp16 each)
    const __half* bptr[2]; uint32_t bdstb[2]; int brow7[2];
    #pragma unroll
    for (int i = 0; i < 2; i++) {
        int s = tid + i * 256;
        int var = s >> 8;
        int row = s & 255;
        bptr[i] = Wf + (size_t)var * wvar + (size_t)(n0 + row) * K;
        bdstb[i] = (uint32_t)(B_OFF + var * B_TILE + row * 128);
        brow7[i] = row & 7;
    }

    // ---- mma lane constants: 8 warps, 2 m-bands x 4 n-bands of 64x64 -------
    const int wm = wid & 1;
    const int wn = wid >> 1;
    const int mbase = wm * 64;
    const int nbase = wn * 64;
    const int a_row_off = ((lane >> 3) & 1) * 8 + (lane & 7);
    const int a_kh = lane >> 4;           // 0..1 within a 16-k step
    const int b_row_off = ((lane >> 4) & 1) * 8 + (lane & 7);
    const int b_h = (lane >> 3) & 1;

    float acc[4][8][4];
    #pragma unroll
    for (int mi = 0; mi < 4; mi++)
        #pragma unroll
        for (int ni = 0; ni < 8; ni++)
            #pragma unroll
            for (int e = 0; e < 4; e++) acc[mi][ni][e] = 0.f;

    auto issue = [&](int it) {
        uint32_t sb = sbase + (it & 1) * STAGE;
        int koff = it * 64;
        #pragma unroll
        for (int c = 0; c < 8; c++)
            cp16(sb + adstb + (uint32_t)((c ^ arow7) << 4), aptr + koff + c * 8);
        #pragma unroll
        for (int i = 0; i < 2; i++)
            #pragma unroll
            for (int c = 0; c < 8; c++)
                cp16(sb + bdstb[i] + (uint32_t)((c ^ brow7[i]) << 4),
                     bptr[i] + koff + c * 8);
        cp_commit();
    };

    const int niter = K >> 6;
    issue(0); issue(1);

    for (int it = 0; it < niter; ++it) {
        cp_wait1();               // group it complete
        __syncthreads();

        const uint32_t base = sbase + (it & 1) * STAGE;
        #pragma unroll
        for (int ks = 0; ks < 4; ks++) {
            // B fragments: 2 variants x 4 ldsm_x4 covering 64 n, this k-step
            uint32_t bb[2][16];
            #pragma unroll
            for (int v = 0; v < 2; v++)
                #pragma unroll
                for (int g = 0; g < 4; g++) {
                    int row = nbase + g * 16 + b_row_off;
                    ldsm_x4(&bb[v][g * 4],
                            base + B_OFF + v * B_TILE + swz128(row, ks * 2 + b_h));
                }
            #pragma unroll
            for (int av = 0; av < 2; av++) {
                uint32_t a[4][4];
                #pragma unroll
                for (int mi = 0; mi < 4; mi++) {
                    int r = mbase + mi * 16 + a_row_off;
                    ldsm_x4(a[mi], base + av * A_TILE + swz128(r, ks * 2 + a_kh));
                }
                #pragma unroll
                for (int ni = 0; ni < 8; ni++)
                    #pragma unroll
                    for (int mi = 0; mi < 4; mi++)
                        mma_fp16(acc[mi][ni], a[mi], &bb[av][ni * 2]);
            }
        }
        __syncthreads();          // all warps done reading this slot
        if (it + 2 < niter) issue(it + 2);
        else cp_commit();         // empty group keeps count uniform
    }

    // ---- epilogue ----------------------------------------------------------
    const int erow = lane >> 2;
    const int ecol = (lane & 3) * 2;
    #pragma unroll
    for (int mi = 0; mi < 4; mi++) {
        int r0 = m0 + mbase + mi * 16 + erow;
        int r1 = r0 + 8;
        #pragma unroll
        for (int ni = 0; ni < 8; ni++) {
            int c = n0 + nbase + ni * 8 + ecol;
            float bx = bias[c], by = bias[c + 1];
            float v00 = acc[mi][ni][0] + bx, v01 = acc[mi][ni][1] + by;
            float v10 = acc[mi][ni][2] + bx, v11 = acc[mi][ni][3] + by;
            if (STAGE2) {
                if (r0 < M) {
                    float2 rr = *(const float2*)(resid + (size_t)r0 * Nfull + c);
                    *(float2*)(outF + (size_t)r0 * Nfull + c) =
                        make_float2(v00 + rr.x, v01 + rr.y);
                }
                if (r1 < M) {
                    float2 rr = *(const float2*)(resid + (size_t)r1 * Nfull + c);
                    *(float2*)(outF + (size_t)r1 * Nfull + c) =
                        make_float2(v10 + rr.x, v11 + rr.y);
                }
            } else {
                if (r0 < M)
                    *(__half2*)(outH + (size_t)r0 * Nfull + c) = __floats2half2_rn(v00, v01);
                if (r1 < M)
                    *(__half2*)(outH + (size_t)r1 * Nfull + c) = __floats2half2_rn(v10, v11);
            }
        }
    }
}

// ---------------------------------------------------------------------------
__global__ __launch_bounds__(256)
void rmsnorm_kernel(const float* __restrict__ pre,
                    const float* __restrict__ gamma,
                    float* __restrict__ out, int E, float invE)
{
    int t = blockIdx.x;
    const float* row = pre + (size_t)t * E;
    float ss = 0.f;
    for (int i = threadIdx.x * 4; i < E; i += blockDim.x * 4) {
        float4 v = *(const float4*)(row + i);
        ss += v.x * v.x + v.y * v.y + v.z * v.z + v.w * v.w;
    }
    __shared__ float red[32];
    #pragma unroll
    for (int o = 16; o; o >>= 1) ss += __shfl_xor_sync(~0u, ss, o);
    if ((threadIdx.x & 31) == 0) red[threadIdx.x >> 5] = ss;
    __syncthreads();
    if (threadIdx.x < 32) {
        float v = (threadIdx.x < (blockDim.x >> 5)) ? red[threadIdx.x] : 0.f;
        #pragma unroll
        for (int o = 16; o; o >>= 1) v += __shfl_xor_sync(~0u, v, o);
        if (threadIdx.x == 0) red[0] = v;
    }
    __syncthreads();
    float scale = rsqrtf(red[0] * invE + 1e-6f);
    for (int i = threadIdx.x * 4; i < E; i += blockDim.x * 4) {
        float4 v = *(const float4*)(row + i);
        float4 g = *(const float4*)(gamma + i);
        v.x *= scale * g.x; v.y *= scale * g.y;
        v.z *= scale * g.z; v.w *= scale * g.w;
        *(float4*)(out + (size_t)t * E + i) = v;
    }
}

__global__ void lf_kernel(const float* __restrict__ inputs,
                          const int* __restrict__ start,
                          const int* __restrict__ lens,
                          int B, int E, int H, int total,
                          float* __restrict__ out, long long out_size)
{
    int b = blockIdx.x;
    int last = start[b] + lens[b] - 1;
    long long base1 = (long long)total * E;
    long long base2 = base1 + (long long)B * E;
    for (int i = threadIdx.x; i < E; i += blockDim.x) {
        long long o = base1 + (long long)b * E + i;
        if (o < out_size) out[o] = inputs[(size_t)last * E + i];
    }
    for (int n = threadIdx.x; n < H; n += blockDim.x) {
        long long o = base2 + (long long)b * H + n;
        if (o < out_size) out[o] = __half2float(g_O1h[(size_t)last * H + n]);
    }
}

__global__ void fallback_kernel(float* out, int n) {
    int i = blockIdx.x * blockDim.x + threadIdx.x;
    if (i < n) out[i] = 0.f;
}

// ---------------------------------------------------------------------------
extern "C" void kernel_launch(void* const* d_in, const int* in_sizes, int n_in,
                              void* d_out, int out_size)
{
    const float* inputs = (const float*)d_in[0];
    const float* lf1    = (const float*)d_in[1];
    const float* lf2    = (const float*)d_in[2];
    const float* w1     = (const float*)d_in[3];
    const float* b1     = (const float*)d_in[4];
    const float* w2     = (const float*)d_in[5];
    const float* b2     = (const float*)d_in[6];
    const float* gamma  = (const float*)d_in[7];
    const int*   start  = (const int*)d_in[8];
    const int*   lens   = (const int*)d_in[9];
    const int*   maxlen = (n_in > 10) ? (const int*)d_in[10] : nullptr;

    const int E = in_sizes[7];
    const int H = in_sizes[4];
    const int total = in_sizes[0] / E;
    const int B = in_sizes[9];
    float* out = (float*)d_out;

    if (E > MAX_E || H > MAX_H || total > MAX_TOTAL || B > MAX_B ||
        (E & 255) || (H & 255) || (E & 63) || (H & 63)) {
        fallback_kernel<<<(out_size + 255) / 256, 256>>>(out, out_size);
        return;
    }

    __half *pXh, *pO1h, *pW1f, *pW2f, *pBXh, *pBOh;
    float *pPre;
    cudaGetSymbolAddress((void**)&pXh,  g_Xh);
    cudaGetSymbolAddress((void**)&pO1h, g_O1h);
    cudaGetSymbolAddress((void**)&pW1f, g_W1f);
    cudaGetSymbolAddress((void**)&pW2f, g_W2f);
    cudaGetSymbolAddress((void**)&pBXh, g_bndXh);
    cudaGetSymbolAddress((void**)&pBOh, g_bndOh);
    cudaGetSymbolAddress((void**)&pPre, g_pre);

    cudaFuncSetAttribute(conv_tc<false>, cudaFuncAttributeMaxDynamicSharedMemorySize, DYN_SMEM);
    cudaFuncSetAttribute(conv_tc<true>,  cudaFuncAttributeMaxDynamicSharedMemorySize, DYN_SMEM);

    split_x_kernel<<<512, 256>>>(inputs, (size_t)total * E);
    pack_w_kernel<<<512, 256>>>(w1, w2, E, H);
    prep_tok_kernel<<<(total + 255) / 256, 256>>>(start, B, total);
    prep_bnd_kernel<<<B, 256>>>(lf1, lf2, w1, b1, lens, maxlen, E, H);

    // Stage 1: O1 = Xprev@W1_0 + X@W1_1 + b1   (M=total, N=H, K=E)
    {
        dim3 grid(H / 256, (total + 127) / 128);
        conv_tc<false><<<grid, 256, DYN_SMEM>>>(pXh, pBXh,
                                                pW1f, (size_t)H * E,
                                                b1, nullptr, start,
                                                total, H, E,
                                                nullptr, pO1h);
    }
    // Stage 2: pre = O1prev@W2_0 + O1@W2_1 + b2 + x (M=total, N=E, K=H)
    {
        dim3 grid(E / 256, (total + 127) / 128);
        conv_tc<true><<<grid, 256, DYN_SMEM>>>(pO1h, pBOh,
                                               pW2f, (size_t)E * H,
                                               b2, inputs, start,
                                               total, E, H,
                                               pPre, nullptr);
    }
    rmsnorm_kernel<<<total, 256>>>(pPre, gamma, out, E, 1.f / (float)E);
    lf_kernel<<<B, 256>>>(inputs, start, lens, B, E, H, total,
                          out, (long long)out_size);
}